// round 3
// baseline (speedup 1.0000x reference)
#include <cuda_runtime.h>

#define HH 384
#define WW 384
#define NPIX (HH * WW)
#define NSW 382     // swaps per row sweep (w = 383..2)
#define NROWS 382   // row sweeps (h = 383..2)

#define SIM_BLOCKS 48          // 8 sweeps per block
#define BLUR_BLOCKS (12 * 48)  // 32x8 tiles

// Scratch (static __device__ globals: allocation-free)
__device__ float g_B1[NPIX];            // blurred input
__device__ int   g_A[NROWS * 2 * WW];   // per-sweep strip permutations (global src indices)

// Gaussian weights: sigma=0.4, radius=2, normalized (double-precision constants)
#define K0D 3.726653172078671e-06
#define K1D 0.04393693362340742
#define KSUM (1.0 + 2.0 * (K0D + K1D))
#define KW0 ((float)(K0D / KSUM))
#define KW1 ((float)(K1D / KSUM))
#define KW2 ((float)(1.0 / KSUM))

// ---------------------------------------------------------------------------
// K1 (merged): blocks [0, SIM_BLOCKS) run the warp-parallel sweep sim;
// blocks [SIM_BLOCKS, SIM_BLOCKS+BLUR_BLOCKS) run the first blur. The two are
// independent, so merging lets them overlap and drops a launch.
//
// Sweep sim recurrence (per sweep h, step s, w = 383 - s):
//   A_{s+1} = (px && !py) ? A_s : c_s      (c_s = h*384 + 382 - s)
//   B_{s+1} = (px &&  py) ? A_s : d_s      (d_s = c_s - 384)
// A is a reset chain -> warp max-scan of last-reset index; B depends only on
// previous step's A/flags -> one shfl. 12 steps/lane, register-local.
// ---------------------------------------------------------------------------
__global__ __launch_bounds__(256) void fused1_kernel(const float* __restrict__ in,
                                                     const int4* __restrict__ offs4) {
    __shared__ float s[12][40];
    __shared__ unsigned char sOff[8 * 384];

    int tid = threadIdx.x;

    if (blockIdx.x < SIM_BLOCKS) {
        // ---- sweep sim: 8 sweeps per block ----
        // Stage offsets: 8 sweeps x 191 int4 (= 382 int2 pairs each), coalesced,
        // converted to 1 byte/step: bit0 = (dx != 0), bit1 = (dy != 0).
        int base4 = blockIdx.x * 8 * 191;          // int4 index into offs
        for (int t = tid; t < 8 * 191; t += 256) {
            if (base4 + t < NROWS * 191) {
                int4 v = offs4[base4 + t];
                int ls = t / 191, st = (t - ls * 191) * 2;
                unsigned b0 = (v.x ? 1u : 0u) | (v.y ? 2u : 0u);
                unsigned b1 = (v.z ? 1u : 0u) | (v.w ? 2u : 0u);
                *(unsigned short*)&sOff[ls * 384 + st] = (unsigned short)(b0 | (b1 << 8));
            }
        }
        __syncthreads();

        int wl = tid >> 5, lane = tid & 31;
        int u = blockIdx.x * 8 + wl;
        if (u >= NROWS) return;
        int h = 383 - u;

        int s0 = 12 * lane;
        int cnt = min(NSW - s0, 12);               // lane 31 -> 10

        // flags from smem: 3 conflict-free u32 reads (bank stride 3)
        const unsigned* fp = (const unsigned*)&sOff[wl * 384 + s0];
        unsigned q0 = fp[0], q1 = fp[1], q2 = fp[2];
        unsigned mpx = 0, mpy = 0;
#pragma unroll
        for (int j = 0; j < 4; j++) {
            mpx |= ((q0 >> (8 * j)) & 1u) << j;
            mpy |= ((q0 >> (8 * j + 1)) & 1u) << j;
            mpx |= ((q1 >> (8 * j)) & 1u) << (j + 4);
            mpy |= ((q1 >> (8 * j + 1)) & 1u) << (j + 4);
            mpx |= ((q2 >> (8 * j)) & 1u) << (j + 8);
            mpy |= ((q2 >> (8 * j + 1)) & 1u) << (j + 8);
        }
        unsigned valid = (cnt >= 12) ? 0xFFFu : ((1u << cnt) - 1u);
        unsigned mrst = (~(mpx & ~mpy)) & valid;   // steps where A resets
        int lr_full = mrst ? (s0 + 31 - __clz(mrst)) : -1;
        unsigned m2 = mrst & ~(1u << (cnt - 1));
        int lr_excl = m2 ? (s0 + 31 - __clz(m2)) : -1;

        // inclusive max-scan, then exclusive carry
        int v = lr_full;
#pragma unroll
        for (int off = 1; off < 32; off <<= 1) {
            int t = __shfl_up_sync(0xFFFFFFFFu, v, off);
            if (lane >= off) v = max(v, t);
        }
        int R_in = __shfl_up_sync(0xFFFFFFFFu, v, 1);
        if (lane == 0) R_in = -1;

        int A = h * WW + 382 - R_in;

        int myA_last = h * WW + 382 - max(R_in, lr_excl);
        unsigned pxl = (mpx >> (cnt - 1)) & 1u, pyl = (mpy >> (cnt - 1)) & 1u;
        int pack = (myA_last << 2) | (int)(pxl << 1) | (int)pyl;
        int prev = __shfl_up_sync(0xFFFFFFFFu, pack, 1);

        int B;
        if (lane == 0) {
            B = (h - 1) * WW + 383;
        } else {
            int A_pl = prev >> 2;
            bool ppx = (prev >> 1) & 1, ppy = prev & 1;
            B = (ppx && ppy) ? A_pl : ((h - 1) * WW + 383 - s0);
        }

        int* __restrict__ A0 = g_A + u * (2 * WW);   // row h-1
        int* __restrict__ A1 = A0 + WW;              // row h
#pragma unroll
        for (int j = 0; j < 12; j++) {
            if (j >= cnt) break;
            int stp = s0 + j, w = 383 - stp;
            int c = h * WW + (w - 1);
            int d = c - WW;
            bool pX = (mpx >> j) & 1u;
            bool pY = (mpy >> j) & 1u;
            int fa = pX ? (pY ? d : c) : (pY ? B : A);
            int fb = (!pX && pY) ? A : B;
            A1[w] = fa;
            A0[w] = fb;
            int nA = (pX && !pY) ? A : c;
            B = (pX && pY) ? A : d;
            A = nA;
        }
        if (lane == 31) {
            A1[1] = A; A0[1] = B;
            A1[0] = h * WW; A0[0] = (h - 1) * WW;
        }
    } else {
        // ---- blur1: fused 2D gaussian (edge replicate) : in -> g_B1 ----
        const float KW[5] = {KW0, KW1, KW2, KW1, KW0};
        int bi = blockIdx.x - SIM_BLOCKS;
        int bx = (bi % 12) * 32, by = (bi / 12) * 8;
        int tx = tid & 31, ty = tid >> 5;

        for (int cell = tid; cell < 12 * 36; cell += 256) {
            int i = cell / 36, j = cell - i * 36;
            int gr = min(max(by + i - 2, 0), HH - 1);
            int gc = min(max(bx + j - 2, 0), WW - 1);
            s[i][j] = in[gr * WW + gc];
        }
        __syncthreads();

        float acc = 0.0f;
#pragma unroll
        for (int i = 0; i < 5; i++) {
            float t = 0.0f;
#pragma unroll
            for (int j = 0; j < 5; j++) t += KW[j] * s[ty + i][tx + j];
            acc += KW[i] * t;
        }
        g_B1[(by + ty) * WW + (bx + tx)] = acc;
    }
}

// ---------------------------------------------------------------------------
// Composed-permutation walk: g(x) = sigma_383(...sigma_2(x)...)
// ---------------------------------------------------------------------------
__device__ __forceinline__ int walk_src(int r0, int c0) {
    int rho = r0, c = c0;
    if (r0 >= 1) {
        int h = (r0 < 2) ? 2 : r0;
        while (true) {
            int lr = rho - (h - 1);   // 0 or 1
            int idx = g_A[(383 - h) * (2 * WW) + lr * WW + c];
            if (idx >= h * WW) {      // stayed on row h -> touched again by h+1
                rho = h;
                c = idx - h * WW;
                if (++h > 383) break;
            } else {                  // dropped to row h-1 -> done forever
                rho = h - 1;
                c = idx - rho * WW;
                break;
            }
        }
    }
    return rho * WW + c;
}

// ---------------------------------------------------------------------------
// K2: fused walk-gather + gaussian blur #2 + clip -> d_out
// ---------------------------------------------------------------------------
__global__ __launch_bounds__(256) void final_kernel(float* __restrict__ out) {
    __shared__ float s[12][40];
    const float KW[5] = {KW0, KW1, KW2, KW1, KW0};

    int bx = blockIdx.x * 32, by = blockIdx.y * 8;
    int tx = threadIdx.x, ty = threadIdx.y;
    int tid = ty * 32 + tx;

    for (int cell = tid; cell < 12 * 36; cell += 256) {
        int i = cell / 36, j = cell - i * 36;
        int gr = min(max(by + i - 2, 0), HH - 1);
        int gc = min(max(bx + j - 2, 0), WW - 1);
        int src = walk_src(gr, gc);
        s[i][j] = g_B1[src];
    }
    __syncthreads();

    float acc = 0.0f;
#pragma unroll
    for (int i = 0; i < 5; i++) {
        float t = 0.0f;
#pragma unroll
        for (int j = 0; j < 5; j++) t += KW[j] * s[ty + i][tx + j];
        acc += KW[i] * t;
    }
    acc = fminf(fmaxf(acc, 0.0f), 1.0f);
    out[(by + ty) * WW + (bx + tx)] = acc;
}

// ---------------------------------------------------------------------------
extern "C" void kernel_launch(void* const* d_in, const int* in_sizes, int n_in,
                              void* d_out, int out_size) {
    const float* img = (const float*)d_in[0];
    const int4* offs4 = (const int4*)d_in[1];   // (145924, 2) int32 pairs, 16B-aligned
    float* out = (float*)d_out;

    fused1_kernel<<<SIM_BLOCKS + BLUR_BLOCKS, 256>>>(img, offs4);

    dim3 blk(32, 8);
    dim3 grd(WW / 32, HH / 8);
    final_kernel<<<grd, blk>>>(out);
}

// round 4
// speedup vs baseline: 1.1360x; 1.1360x over previous
#include <cuda_runtime.h>

#define HH 384
#define WW 384
#define NPIX (HH * WW)
#define NSW 382     // swaps per row sweep (w = 383..2)
#define NROWS 382   // row sweeps (h = 383..2)

#define SIM_BLOCKS 48          // 8 sweeps per block
#define BLUR_BLOCKS (12 * 48)  // 32x8 tiles for blur1

#define NSTRIP 28              // strips staged per final block

// Scratch (static __device__ globals: allocation-free)
__device__ float g_B1[NPIX];                        // blurred input
__device__ unsigned short g_A16[NROWS * 2 * WW];    // strip perms, compressed:
                                                    // bit15 = stays-on-row-h, bits[0:9] = column

// Gaussian weights: sigma=0.4, radius=2, normalized
#define K0D 3.726653172078671e-06
#define K1D 0.04393693362340742
#define KSUM (1.0 + 2.0 * (K0D + K1D))
#define KW0 ((float)(K0D / KSUM))
#define KW1 ((float)(K1D / KSUM))
#define KW2 ((float)(1.0 / KSUM))

__device__ __forceinline__ unsigned short enc_idx(int idx, int h) {
    int stay = idx >= h * WW;
    int col = idx - (stay ? h * WW : (h - 1) * WW);
    return (unsigned short)(col | (stay << 15));
}

// ---------------------------------------------------------------------------
// K1 (merged): blocks [0,48) = warp-parallel sweep sim; rest = blur1.
// ---------------------------------------------------------------------------
__global__ __launch_bounds__(256) void fused1_kernel(const float* __restrict__ in,
                                                     const int4* __restrict__ offs4) {
    __shared__ float s[12][40];
    __shared__ unsigned char sOff[8 * 384];

    int tid = threadIdx.x;

    if (blockIdx.x < SIM_BLOCKS) {
        // Stage offsets coalesced; 1 byte/step: bit0=(dx!=0), bit1=(dy!=0).
        int base4 = blockIdx.x * 8 * 191;
        for (int t = tid; t < 8 * 191; t += 256) {
            if (base4 + t < NROWS * 191) {
                int4 v = offs4[base4 + t];
                int ls = t / 191, st = (t - ls * 191) * 2;
                unsigned b0 = (v.x ? 1u : 0u) | (v.y ? 2u : 0u);
                unsigned b1 = (v.z ? 1u : 0u) | (v.w ? 2u : 0u);
                *(unsigned short*)&sOff[ls * 384 + st] = (unsigned short)(b0 | (b1 << 8));
            }
        }
        __syncthreads();

        int wl = tid >> 5, lane = tid & 31;
        int u = blockIdx.x * 8 + wl;
        if (u >= NROWS) return;
        int h = 383 - u;

        int s0 = 12 * lane;
        int cnt = min(NSW - s0, 12);               // lane 31 -> 10

        const unsigned* fp = (const unsigned*)&sOff[wl * 384 + s0];
        unsigned q0 = fp[0], q1 = fp[1], q2 = fp[2];
        unsigned mpx = 0, mpy = 0;
#pragma unroll
        for (int j = 0; j < 4; j++) {
            mpx |= ((q0 >> (8 * j)) & 1u) << j;
            mpy |= ((q0 >> (8 * j + 1)) & 1u) << j;
            mpx |= ((q1 >> (8 * j)) & 1u) << (j + 4);
            mpy |= ((q1 >> (8 * j + 1)) & 1u) << (j + 4);
            mpx |= ((q2 >> (8 * j)) & 1u) << (j + 8);
            mpy |= ((q2 >> (8 * j + 1)) & 1u) << (j + 8);
        }
        unsigned valid = (cnt >= 12) ? 0xFFFu : ((1u << cnt) - 1u);
        unsigned mrst = (~(mpx & ~mpy)) & valid;   // steps where A resets
        int lr_full = mrst ? (s0 + 31 - __clz(mrst)) : -1;
        unsigned m2 = mrst & ~(1u << (cnt - 1));
        int lr_excl = m2 ? (s0 + 31 - __clz(m2)) : -1;

        int v = lr_full;
#pragma unroll
        for (int off = 1; off < 32; off <<= 1) {
            int t = __shfl_up_sync(0xFFFFFFFFu, v, off);
            if (lane >= off) v = max(v, t);
        }
        int R_in = __shfl_up_sync(0xFFFFFFFFu, v, 1);
        if (lane == 0) R_in = -1;

        int A = h * WW + 382 - R_in;

        int myA_last = h * WW + 382 - max(R_in, lr_excl);
        unsigned pxl = (mpx >> (cnt - 1)) & 1u, pyl = (mpy >> (cnt - 1)) & 1u;
        int pack = (myA_last << 2) | (int)(pxl << 1) | (int)pyl;
        int prev = __shfl_up_sync(0xFFFFFFFFu, pack, 1);

        int B;
        if (lane == 0) {
            B = (h - 1) * WW + 383;
        } else {
            int A_pl = prev >> 2;
            bool ppx = (prev >> 1) & 1, ppy = prev & 1;
            B = (ppx && ppy) ? A_pl : ((h - 1) * WW + 383 - s0);
        }

        unsigned short* __restrict__ A0 = g_A16 + u * (2 * WW);   // row h-1 (lr=0)
        unsigned short* __restrict__ A1 = A0 + WW;                // row h   (lr=1)
#pragma unroll
        for (int j = 0; j < 12; j++) {
            if (j >= cnt) break;
            int stp = s0 + j, w = 383 - stp;
            int c = h * WW + (w - 1);
            int d = c - WW;
            bool pX = (mpx >> j) & 1u;
            bool pY = (mpy >> j) & 1u;
            int fa = pX ? (pY ? d : c) : (pY ? B : A);
            int fb = (!pX && pY) ? A : B;
            A1[w] = enc_idx(fa, h);
            A0[w] = enc_idx(fb, h);
            int nA = (pX && !pY) ? A : c;
            B = (pX && pY) ? A : d;
            A = nA;
        }
        if (lane == 31) {
            A1[1] = enc_idx(A, h); A0[1] = enc_idx(B, h);
            A1[0] = (unsigned short)0x8000u; A0[0] = 0;
        }
    } else {
        // blur1: fused 2D gaussian (edge replicate) : in -> g_B1
        const float KW[5] = {KW0, KW1, KW2, KW1, KW0};
        int bi = blockIdx.x - SIM_BLOCKS;
        int bx = (bi % 12) * 32, by = (bi / 12) * 8;
        int tx = tid & 31, ty = tid >> 5;

        for (int cell = tid; cell < 12 * 36; cell += 256) {
            int i = cell / 36, j = cell - i * 36;
            int gr = min(max(by + i - 2, 0), HH - 1);
            int gc = min(max(bx + j - 2, 0), WW - 1);
            s[i][j] = in[gr * WW + gc];
        }
        __syncthreads();

        float acc = 0.0f;
#pragma unroll
        for (int i = 0; i < 5; i++) {
            float t = 0.0f;
#pragma unroll
            for (int j = 0; j < 5; j++) t += KW[j] * s[ty + i][tx + j];
            acc += KW[i] * t;
        }
        g_B1[(by + ty) * WW + (bx + tx)] = acc;
    }
}

// ---------------------------------------------------------------------------
// Walk: band-resident hops (smem), rare tail falls back to global g_A16.
// band mirrors g_A16 strips u in [u_min, u_min + n_h), contiguous.
// ---------------------------------------------------------------------------
__device__ __forceinline__ int walk_band(int r0, int c0,
                                         const unsigned short* __restrict__ band,
                                         int u_min, int h_hi) {
    if (r0 == 0) return c0;
    int h = (r0 < 2) ? 2 : r0;
    int rho = r0, c = c0;
    while (true) {
        if (h > h_hi) {                          // rare fallback: continue in global
            while (true) {
                int lr = rho - (h - 1);
                unsigned e = g_A16[(383 - h) * (2 * WW) + lr * WW + c];
                c = e & 511;
                if (e & 0x8000u) { rho = h; if (++h > 383) break; }
                else { rho = h - 1; break; }
            }
            break;
        }
        int lr = rho - (h - 1);
        unsigned e = band[(383 - h - u_min) * (2 * WW) + lr * WW + c];
        c = e & 511;
        if (e & 0x8000u) { rho = h; if (++h > 383) break; }
        else { rho = h - 1; break; }
    }
    return rho * WW + c;
}

// ---------------------------------------------------------------------------
// K2: 64x8 tiles, 512 threads. Stage strip band -> walk-gather halo tile ->
// gaussian blur #2 -> clip -> out.
// ---------------------------------------------------------------------------
__global__ __launch_bounds__(512) void final_kernel(float* __restrict__ out) {
    __shared__ float s[12][72];
    __shared__ __align__(16) unsigned short band[NSTRIP * 2 * WW];
    const float KW[5] = {KW0, KW1, KW2, KW1, KW0};

    int bx = blockIdx.x * 64, by = blockIdx.y * 8;
    int tid = threadIdx.x;

    int h_lo = (by - 2 < 2) ? 2 : (by - 2);
    int n_h = min(NSTRIP, 384 - h_lo);
    int h_hi = h_lo + n_h - 1;
    int u_min = 383 - h_hi;

    // contiguous vectorized band copy: n_h strips x 96 uint4 each
    {
        const uint4* gsrc = (const uint4*)(g_A16) + (size_t)u_min * 96;
        uint4* bdst = (uint4*)band;
        int tot = n_h * 96;
        for (int t = tid; t < tot; t += 512) bdst[t] = gsrc[t];
    }
    __syncthreads();

    // walk-gather the 12x68 halo tile
    for (int cell = tid; cell < 12 * 68; cell += 512) {
        int i = cell / 68, j = cell - i * 68;
        int gr = min(max(by + i - 2, 0), HH - 1);
        int gc = min(max(bx + j - 2, 0), WW - 1);
        int src = walk_band(gr, gc, band, u_min, h_hi);
        s[i][j] = g_B1[src];
    }
    __syncthreads();

    int tx = tid & 63, ty = tid >> 6;
    float acc = 0.0f;
#pragma unroll
    for (int i = 0; i < 5; i++) {
        float t = 0.0f;
#pragma unroll
        for (int j = 0; j < 5; j++) t += KW[j] * s[ty + i][tx + j];
        acc += KW[i] * t;
    }
    acc = fminf(fmaxf(acc, 0.0f), 1.0f);
    out[(by + ty) * WW + (bx + tx)] = acc;
}

// ---------------------------------------------------------------------------
extern "C" void kernel_launch(void* const* d_in, const int* in_sizes, int n_in,
                              void* d_out, int out_size) {
    const float* img = (const float*)d_in[0];
    const int4* offs4 = (const int4*)d_in[1];   // (145924, 2) int32 pairs, 16B-aligned
    float* out = (float*)d_out;

    fused1_kernel<<<SIM_BLOCKS + BLUR_BLOCKS, 256>>>(img, offs4);

    dim3 blk(512);
    dim3 grd(WW / 64, HH / 8);
    final_kernel<<<grd, blk>>>(out);
}

// round 6
// speedup vs baseline: 1.2854x; 1.1315x over previous
#include <cuda_runtime.h>

#define HH 384
#define WW 384
#define NPIX (HH * WW)
#define NSW 382     // swaps per row sweep (w = 383..2)
#define NROWS 382   // row sweeps (h = 383..2)

#define SIM_BLOCKS 48          // 8 sweeps per block
#define BLUR_BLOCKS (12 * 48)  // 32x8 tiles for blur1

#define NSTRIP 28              // strips staged per final block

// Scratch (static __device__ globals: allocation-free)
__device__ float g_B1[NPIX];                        // blurred input
__device__ unsigned short g_A16[NROWS * 2 * WW];    // strip perms, compressed:
                                                    // bit15 = stays-on-row-h, bits[0:9] = column

// Gaussian weights: sigma=0.4, radius=2, normalized
#define K0D 3.726653172078671e-06
#define K1D 0.04393693362340742
#define KSUM (1.0 + 2.0 * (K0D + K1D))
#define KW0 ((float)(K0D / KSUM))
#define KW1 ((float)(K1D / KSUM))
#define KW2 ((float)(1.0 / KSUM))

__device__ __forceinline__ unsigned short enc_idx(int idx, int h) {
    int stay = idx >= h * WW;
    int col = idx - (stay ? h * WW : (h - 1) * WW);
    return (unsigned short)(col | (stay << 15));
}

// ---------------------------------------------------------------------------
// K1 (merged): blocks [0,48) = warp-parallel sweep sim; rest = blur1.
// Sim writes strips into smem (cheap STS) and flushes to g_A16 with
// coalesced uint4 stores — replaces ~295K scattered STG.U16.
// ---------------------------------------------------------------------------
__global__ __launch_bounds__(256) void fused1_kernel(const float* __restrict__ in,
                                                     const int4* __restrict__ offs4) {
    __shared__ float s[12][40];
    __shared__ float hT[12][32];
    __shared__ unsigned char sOff[8 * 384];
    __shared__ __align__(16) unsigned short sStrip[8 * 2 * WW];   // 12 KB

    int tid = threadIdx.x;

    if (blockIdx.x < SIM_BLOCKS) {
        // Stage offsets coalesced; 1 byte/step: bit0=(dx!=0), bit1=(dy!=0).
        int base4 = blockIdx.x * 8 * 191;
        for (int t = tid; t < 8 * 191; t += 256) {
            if (base4 + t < NROWS * 191) {
                int4 v = offs4[base4 + t];
                int ls = t / 191, st = (t - ls * 191) * 2;
                unsigned b0 = (v.x ? 1u : 0u) | (v.y ? 2u : 0u);
                unsigned b1 = (v.z ? 1u : 0u) | (v.w ? 2u : 0u);
                *(unsigned short*)&sOff[ls * 384 + st] = (unsigned short)(b0 | (b1 << 8));
            }
        }
        __syncthreads();

        int wl = tid >> 5, lane = tid & 31;
        int u = blockIdx.x * 8 + wl;

        if (u < NROWS) {
            int h = 383 - u;
            int s0 = 12 * lane;
            int cnt = min(NSW - s0, 12);               // lane 31 -> 10

            const unsigned* fp = (const unsigned*)&sOff[wl * 384 + s0];
            unsigned q0 = fp[0], q1 = fp[1], q2 = fp[2];
            unsigned mpx = 0, mpy = 0;
#pragma unroll
            for (int j = 0; j < 4; j++) {
                mpx |= ((q0 >> (8 * j)) & 1u) << j;
                mpy |= ((q0 >> (8 * j + 1)) & 1u) << j;
                mpx |= ((q1 >> (8 * j)) & 1u) << (j + 4);
                mpy |= ((q1 >> (8 * j + 1)) & 1u) << (j + 4);
                mpx |= ((q2 >> (8 * j)) & 1u) << (j + 8);
                mpy |= ((q2 >> (8 * j + 1)) & 1u) << (j + 8);
            }
            unsigned valid = (cnt >= 12) ? 0xFFFu : ((1u << cnt) - 1u);
            unsigned mrst = (~(mpx & ~mpy)) & valid;   // steps where A resets
            int lr_full = mrst ? (s0 + 31 - __clz(mrst)) : -1;
            unsigned m2 = mrst & ~(1u << (cnt - 1));
            int lr_excl = m2 ? (s0 + 31 - __clz(m2)) : -1;

            int v = lr_full;
#pragma unroll
            for (int off = 1; off < 32; off <<= 1) {
                int t = __shfl_up_sync(0xFFFFFFFFu, v, off);
                if (lane >= off) v = max(v, t);
            }
            int R_in = __shfl_up_sync(0xFFFFFFFFu, v, 1);
            if (lane == 0) R_in = -1;

            int A = h * WW + 382 - R_in;

            int myA_last = h * WW + 382 - max(R_in, lr_excl);
            unsigned pxl = (mpx >> (cnt - 1)) & 1u, pyl = (mpy >> (cnt - 1)) & 1u;
            int pack = (myA_last << 2) | (int)(pxl << 1) | (int)pyl;
            int prev = __shfl_up_sync(0xFFFFFFFFu, pack, 1);

            int B;
            if (lane == 0) {
                B = (h - 1) * WW + 383;
            } else {
                int A_pl = prev >> 2;
                bool ppx = (prev >> 1) & 1, ppy = prev & 1;
                B = (ppx && ppy) ? A_pl : ((h - 1) * WW + 383 - s0);
            }

            unsigned short* __restrict__ A0 = sStrip + wl * (2 * WW);   // row h-1
            unsigned short* __restrict__ A1 = A0 + WW;                  // row h
#pragma unroll
            for (int j = 0; j < 12; j++) {
                if (j >= cnt) break;
                int stp = s0 + j, w = 383 - stp;
                int c = h * WW + (w - 1);
                int d = c - WW;
                bool pX = (mpx >> j) & 1u;
                bool pY = (mpy >> j) & 1u;
                int fa = pX ? (pY ? d : c) : (pY ? B : A);
                int fb = (!pX && pY) ? A : B;
                A1[w] = enc_idx(fa, h);
                A0[w] = enc_idx(fb, h);
                int nA = (pX && !pY) ? A : c;
                B = (pX && pY) ? A : d;
                A = nA;
            }
            if (lane == 31) {
                A1[1] = enc_idx(A, h); A0[1] = enc_idx(B, h);
                A1[0] = (unsigned short)0x8000u; A0[0] = 0;
            }
        }
        __syncthreads();

        // coalesced flush: 8 strips x 96 uint4 = 768 uint4 (3 per thread)
        {
            int base = blockIdx.x * 768;               // uint4 units into g_A16
            const uint4* src = (const uint4*)sStrip;
            uint4* dst = (uint4*)g_A16;
            for (int t = tid; t < 768; t += 256) {
                if (base + t < NROWS * 96) dst[base + t] = src[t];
            }
        }
    } else {
        // blur1: two-pass separable gaussian (edge replicate) : in -> g_B1
        int bi = blockIdx.x - SIM_BLOCKS;
        int bx = (bi % 12) * 32, by = (bi / 12) * 8;
        int tx = tid & 31, ty = tid >> 5;

        for (int cell = tid; cell < 12 * 36; cell += 256) {
            int i = cell / 36, j = cell - i * 36;
            int gr = min(max(by + i - 2, 0), HH - 1);
            int gc = min(max(bx + j - 2, 0), WW - 1);
            s[i][j] = in[gr * WW + gc];
        }
        __syncthreads();

        for (int cell = tid; cell < 12 * 32; cell += 256) {
            int i = cell >> 5, j = cell & 31;
            hT[i][j] = KW0 * (s[i][j] + s[i][j + 4]) +
                       KW1 * (s[i][j + 1] + s[i][j + 3]) + KW2 * s[i][j + 2];
        }
        __syncthreads();

        float acc = KW0 * (hT[ty][tx] + hT[ty + 4][tx]) +
                    KW1 * (hT[ty + 1][tx] + hT[ty + 3][tx]) + KW2 * hT[ty + 2][tx];
        g_B1[(by + ty) * WW + (bx + tx)] = acc;
    }
}

// ---------------------------------------------------------------------------
// Walk: band-resident hops (smem), rare tail falls back to global g_A16.
// ---------------------------------------------------------------------------
__device__ __forceinline__ int walk_band(int r0, int c0,
                                         const unsigned short* __restrict__ band,
                                         int u_min, int h_hi) {
    if (r0 == 0) return c0;
    int h = (r0 < 2) ? 2 : r0;
    int rho = r0, c = c0;
    while (true) {
        if (h > h_hi) {                          // rare fallback: continue in global
            while (true) {
                int lr = rho - (h - 1);
                unsigned e = g_A16[(383 - h) * (2 * WW) + lr * WW + c];
                c = e & 511;
                if (e & 0x8000u) { rho = h; if (++h > 383) break; }
                else { rho = h - 1; break; }
            }
            break;
        }
        int lr = rho - (h - 1);
        unsigned e = band[(383 - h - u_min) * (2 * WW) + lr * WW + c];
        c = e & 511;
        if (e & 0x8000u) { rho = h; if (++h > 383) break; }
        else { rho = h - 1; break; }
    }
    return rho * WW + c;
}

// ---------------------------------------------------------------------------
// K2: 64x8 tiles, 512 threads. Stage strip band -> walk-gather halo tile ->
// two-pass gaussian blur -> clip -> out.
// hT (horizontal-pass buffer) ALIASES band: band is dead once all walks have
// completed (guarded by the __syncthreads between phases). Keeps static smem
// at 46,464 B < 48 KB.
// ---------------------------------------------------------------------------
__global__ __launch_bounds__(512) void final_kernel(float* __restrict__ out) {
    __shared__ float s[12][72];
    __shared__ __align__(16) unsigned short band[NSTRIP * 2 * WW];  // 43 KB
    int bx = blockIdx.x * 64, by = blockIdx.y * 8;
    int tid = threadIdx.x;

    int h_lo = (by - 2 < 2) ? 2 : (by - 2);
    int n_h = min(NSTRIP, 384 - h_lo);
    int h_hi = h_lo + n_h - 1;
    int u_min = 383 - h_hi;

    // contiguous vectorized band copy: n_h strips x 96 uint4 each
    {
        const uint4* gsrc = (const uint4*)(g_A16) + (size_t)u_min * 96;
        uint4* bdst = (uint4*)band;
        int tot = n_h * 96;
        for (int t = tid; t < tot; t += 512) bdst[t] = gsrc[t];
    }
    __syncthreads();

    // walk-gather the 12x68 halo tile
    for (int cell = tid; cell < 12 * 68; cell += 512) {
        int i = cell / 68, j = cell - i * 68;
        int gr = min(max(by + i - 2, 0), HH - 1);
        int gc = min(max(bx + j - 2, 0), WW - 1);
        int src = walk_band(gr, gc, band, u_min, h_hi);
        s[i][j] = g_B1[src];
    }
    __syncthreads();   // all walks done -> band storage reusable

    float (*hT)[64] = (float (*)[64])band;   // alias: 12*64*4 = 3 KB of 43 KB

    // horizontal pass: 12 x 64
    for (int cell = tid; cell < 12 * 64; cell += 512) {
        int i = cell >> 6, j = cell & 63;
        hT[i][j] = KW0 * (s[i][j] + s[i][j + 4]) +
                   KW1 * (s[i][j + 1] + s[i][j + 3]) + KW2 * s[i][j + 2];
    }
    __syncthreads();

    // vertical pass + clip
    int tx = tid & 63, ty = tid >> 6;
    float acc = KW0 * (hT[ty][tx] + hT[ty + 4][tx]) +
                KW1 * (hT[ty + 1][tx] + hT[ty + 3][tx]) + KW2 * hT[ty + 2][tx];
    acc = fminf(fmaxf(acc, 0.0f), 1.0f);
    out[(by + ty) * WW + (bx + tx)] = acc;
}

// ---------------------------------------------------------------------------
extern "C" void kernel_launch(void* const* d_in, const int* in_sizes, int n_in,
                              void* d_out, int out_size) {
    const float* img = (const float*)d_in[0];
    const int4* offs4 = (const int4*)d_in[1];   // (145924, 2) int32 pairs, 16B-aligned
    float* out = (float*)d_out;

    fused1_kernel<<<SIM_BLOCKS + BLUR_BLOCKS, 256>>>(img, offs4);

    dim3 blk(512);
    dim3 grd(WW / 64, HH / 8);
    final_kernel<<<grd, blk>>>(out);
}

// round 7
// speedup vs baseline: 1.3351x; 1.0387x over previous
#include <cuda_runtime.h>

#define HH 384
#define WW 384
#define NPIX (HH * WW)
#define NSW 382     // swaps per row sweep (w = 383..2)
#define NROWS 382   // row sweeps (h = 383..2)

#define SIM_BLOCKS 48          // 8 sweeps per block
#define BLUR_BLOCKS (12 * 48)  // 32x8 tiles for blur1

#define NSTRIP 28              // strips staged per final block

// Scratch (static __device__ globals: allocation-free)
__device__ float g_B1[NPIX];                        // blurred input
__device__ unsigned short g_A16[NROWS * 2 * WW];    // strip perms, compressed:
                                                    // bit15 = stays-on-row-h, bits[0:9] = column

// Gaussian weights: sigma=0.4, radius=2, normalized
#define K0D 3.726653172078671e-06
#define K1D 0.04393693362340742
#define KSUM (1.0 + 2.0 * (K0D + K1D))
#define KW0 ((float)(K0D / KSUM))
#define KW1 ((float)(K1D / KSUM))
#define KW2 ((float)(1.0 / KSUM))

__device__ __forceinline__ unsigned short enc_idx(int idx, int h) {
    int stay = idx >= h * WW;
    int col = idx - (stay ? h * WW : (h - 1) * WW);
    return (unsigned short)(col | (stay << 15));
}

// ---------------------------------------------------------------------------
// K1 (merged): blocks [0,48) = warp-parallel sweep sim; rest = blur1.
// ---------------------------------------------------------------------------
__global__ __launch_bounds__(256) void fused1_kernel(const float* __restrict__ in,
                                                     const int4* __restrict__ offs4) {
    __shared__ float s[12][40];
    __shared__ float hT[12][32];
    __shared__ unsigned char sOff[8 * 384];
    __shared__ __align__(16) unsigned short sStrip[8 * 2 * WW];   // 12 KB

    int tid = threadIdx.x;

    if (blockIdx.x < SIM_BLOCKS) {
        // Stage offsets coalesced; 1 byte/step: bit0=(dx!=0), bit1=(dy!=0).
        int base4 = blockIdx.x * 8 * 191;
        for (int t = tid; t < 8 * 191; t += 256) {
            if (base4 + t < NROWS * 191) {
                int4 v = offs4[base4 + t];
                int ls = t / 191, st = (t - ls * 191) * 2;
                unsigned b0 = (v.x ? 1u : 0u) | (v.y ? 2u : 0u);
                unsigned b1 = (v.z ? 1u : 0u) | (v.w ? 2u : 0u);
                *(unsigned short*)&sOff[ls * 384 + st] = (unsigned short)(b0 | (b1 << 8));
            }
        }
        __syncthreads();

        int wl = tid >> 5, lane = tid & 31;
        int u = blockIdx.x * 8 + wl;

        if (u < NROWS) {
            int h = 383 - u;
            int s0 = 12 * lane;
            int cnt = min(NSW - s0, 12);               // lane 31 -> 10

            const unsigned* fp = (const unsigned*)&sOff[wl * 384 + s0];
            unsigned q0 = fp[0], q1 = fp[1], q2 = fp[2];
            unsigned mpx = 0, mpy = 0;
#pragma unroll
            for (int j = 0; j < 4; j++) {
                mpx |= ((q0 >> (8 * j)) & 1u) << j;
                mpy |= ((q0 >> (8 * j + 1)) & 1u) << j;
                mpx |= ((q1 >> (8 * j)) & 1u) << (j + 4);
                mpy |= ((q1 >> (8 * j + 1)) & 1u) << (j + 4);
                mpx |= ((q2 >> (8 * j)) & 1u) << (j + 8);
                mpy |= ((q2 >> (8 * j + 1)) & 1u) << (j + 8);
            }
            unsigned valid = (cnt >= 12) ? 0xFFFu : ((1u << cnt) - 1u);
            unsigned mrst = (~(mpx & ~mpy)) & valid;   // steps where A resets
            int lr_full = mrst ? (s0 + 31 - __clz(mrst)) : -1;
            unsigned m2 = mrst & ~(1u << (cnt - 1));
            int lr_excl = m2 ? (s0 + 31 - __clz(m2)) : -1;

            int v = lr_full;
#pragma unroll
            for (int off = 1; off < 32; off <<= 1) {
                int t = __shfl_up_sync(0xFFFFFFFFu, v, off);
                if (lane >= off) v = max(v, t);
            }
            int R_in = __shfl_up_sync(0xFFFFFFFFu, v, 1);
            if (lane == 0) R_in = -1;

            int A = h * WW + 382 - R_in;

            int myA_last = h * WW + 382 - max(R_in, lr_excl);
            unsigned pxl = (mpx >> (cnt - 1)) & 1u, pyl = (mpy >> (cnt - 1)) & 1u;
            int pack = (myA_last << 2) | (int)(pxl << 1) | (int)pyl;
            int prev = __shfl_up_sync(0xFFFFFFFFu, pack, 1);

            int B;
            if (lane == 0) {
                B = (h - 1) * WW + 383;
            } else {
                int A_pl = prev >> 2;
                bool ppx = (prev >> 1) & 1, ppy = prev & 1;
                B = (ppx && ppy) ? A_pl : ((h - 1) * WW + 383 - s0);
            }

            unsigned short* __restrict__ A0 = sStrip + wl * (2 * WW);   // row h-1
            unsigned short* __restrict__ A1 = A0 + WW;                  // row h
#pragma unroll
            for (int j = 0; j < 12; j++) {
                if (j >= cnt) break;
                int stp = s0 + j, w = 383 - stp;
                int c = h * WW + (w - 1);
                int d = c - WW;
                bool pX = (mpx >> j) & 1u;
                bool pY = (mpy >> j) & 1u;
                int fa = pX ? (pY ? d : c) : (pY ? B : A);
                int fb = (!pX && pY) ? A : B;
                A1[w] = enc_idx(fa, h);
                A0[w] = enc_idx(fb, h);
                int nA = (pX && !pY) ? A : c;
                B = (pX && pY) ? A : d;
                A = nA;
            }
            if (lane == 31) {
                A1[1] = enc_idx(A, h); A0[1] = enc_idx(B, h);
                A1[0] = (unsigned short)0x8000u; A0[0] = 0;
            }
        }
        __syncthreads();

        // coalesced flush: 8 strips x 96 uint4 = 768 uint4 (3 per thread)
        {
            int base = blockIdx.x * 768;               // uint4 units into g_A16
            const uint4* src = (const uint4*)sStrip;
            uint4* dst = (uint4*)g_A16;
            for (int t = tid; t < 768; t += 256) {
                if (base + t < NROWS * 96) dst[base + t] = src[t];
            }
        }
    } else {
        // blur1: two-pass separable gaussian (edge replicate) : in -> g_B1
        int bi = blockIdx.x - SIM_BLOCKS;
        int bx = (bi % 12) * 32, by = (bi / 12) * 8;
        int tx = tid & 31, ty = tid >> 5;

        for (int cell = tid; cell < 12 * 36; cell += 256) {
            int i = cell / 36, j = cell - i * 36;
            int gr = min(max(by + i - 2, 0), HH - 1);
            int gc = min(max(bx + j - 2, 0), WW - 1);
            s[i][j] = in[gr * WW + gc];
        }
        __syncthreads();

        for (int cell = tid; cell < 12 * 32; cell += 256) {
            int i = cell >> 5, j = cell & 31;
            hT[i][j] = KW0 * (s[i][j] + s[i][j + 4]) +
                       KW1 * (s[i][j + 1] + s[i][j + 3]) + KW2 * s[i][j + 2];
        }
        __syncthreads();

        float acc = KW0 * (hT[ty][tx] + hT[ty + 4][tx]) +
                    KW1 * (hT[ty + 1][tx] + hT[ty + 3][tx]) + KW2 * hT[ty + 2][tx];
        g_B1[(by + ty) * WW + (bx + tx)] = acc;
    }
}

// ---------------------------------------------------------------------------
// Rare global-fallback continuation of a chain beyond the staged band.
// Enter with walker on row (h_enter - 1), column c.
// ---------------------------------------------------------------------------
__device__ __noinline__ int walk_global(int h_enter, int c) {
    int h = h_enter, rho = h_enter - 1;
    while (h <= 383) {
        unsigned e = g_A16[(383 - h) * (2 * WW) + (rho - (h - 1)) * WW + c];
        c = e & 511;
        if (e & 0x8000u) { rho = h; h++; }
        else { rho = h - 1; break; }
    }
    return rho * WW + c;
}

// ---------------------------------------------------------------------------
// K2: 64x8 tiles, 512 threads. Stage strip band -> dual-chain walk-gather ->
// two-pass gaussian blur -> clip -> out.
// Band coordinates: strip h lives at band rows (h_hi-h)*2 + {0,1} (384 ushort
// per row). First hop reads local row 1 (or 0 when gr==1); every later hop
// reads local row 0, so a hop is: e=band[idx]; c=e&511; stay? bb-=2 : done.
// hT aliases band (dead after walks) to stay under the 48 KB static limit.
// ---------------------------------------------------------------------------
__global__ __launch_bounds__(512) void final_kernel(float* __restrict__ out) {
    __shared__ float s[12][72];
    __shared__ __align__(16) unsigned short band[NSTRIP * 2 * WW];  // 43 KB
    int bx = blockIdx.x * 64, by = blockIdx.y * 8;
    int tid = threadIdx.x;

    int h_lo = (by - 2 < 2) ? 2 : (by - 2);
    int n_h = min(NSTRIP, 384 - h_lo);
    int h_hi = h_lo + n_h - 1;
    int u_min = 383 - h_hi;

    // contiguous vectorized band copy: n_h strips x 96 uint4 each
    {
        const uint4* gsrc = (const uint4*)(g_A16) + (size_t)u_min * 96;
        uint4* bdst = (uint4*)band;
        int tot = n_h * 96;
        for (int t = tid; t < tot; t += 512) bdst[t] = gsrc[t];
    }
    __syncthreads();

    // ---- dual-chain walk: thread owns cells tid and tid+512 of 12x68 ----
    {
        int cell0 = tid, cell1 = tid + 512;
        bool act1 = (cell1 < 12 * 68);

        int i0 = cell0 / 68, j0 = cell0 - i0 * 68;
        int gr0 = min(max(by + i0 - 2, 0), HH - 1);
        int gc0 = min(max(bx + j0 - 2, 0), WW - 1);
        int i1 = 0, j1 = 0, gr1 = 0, gc1 = 0;
        if (act1) {
            i1 = cell1 / 68; j1 = cell1 - i1 * 68;
            gr1 = min(max(by + i1 - 2, 0), HH - 1);
            gc1 = min(max(bx + j1 - 2, 0), WW - 1);
        }

        // init chain state: done/fallback flags, band index, column, base
        int c0 = gc0, bb0 = 0, idx0 = 0, src0 = gc0;
        bool d0 = (gr0 == 0), f0 = false;
        if (!d0) {
            int h0 = (gr0 < 2) ? 2 : gr0;
            int lr = gr0 - (h0 - 1);               // 1 normally, 0 for gr0==1
            bb0 = (h_hi - h0) * 2;
            idx0 = (bb0 + lr) * WW + c0;
        }
        int c1 = gc1, bb1 = 0, idx1 = 0, src1 = gc1;
        bool d1 = (!act1) || (gr1 == 0), f1 = false;
        if (!d1) {
            int h1 = (gr1 < 2) ? 2 : gr1;
            int lr = gr1 - (h1 - 1);
            bb1 = (h_hi - h1) * 2;
            idx1 = (bb1 + lr) * WW + c1;
        }

        while (!(d0 && d1)) {
            unsigned e0 = 0, e1 = 0;
            if (!d0) e0 = band[idx0];
            if (!d1) e1 = band[idx1];
            if (!d0) {
                c0 = e0 & 511;
                if (e0 & 0x8000u) {
                    bb0 -= 2;
                    if (bb0 < 0) { f0 = true; d0 = true; }
                    else idx0 = bb0 * WW + c0;
                } else {
                    src0 = (h_hi - (bb0 >> 1) - 1) * WW + c0;
                    d0 = true;
                }
            }
            if (!d1) {
                c1 = e1 & 511;
                if (e1 & 0x8000u) {
                    bb1 -= 2;
                    if (bb1 < 0) { f1 = true; d1 = true; }
                    else idx1 = bb1 * WW + c1;
                } else {
                    src1 = (h_hi - (bb1 >> 1) - 1) * WW + c1;
                    d1 = true;
                }
            }
        }
        if (f0) src0 = walk_global(h_hi + 1, c0);
        if (f1) src1 = walk_global(h_hi + 1, c1);

        // batched gathers (MLP 2), then STS
        float v0 = g_B1[src0];
        float v1 = act1 ? g_B1[src1] : 0.0f;
        s[i0][j0] = v0;
        if (act1) s[i1][j1] = v1;
    }
    __syncthreads();   // all walks done -> band storage reusable

    float (*hT)[64] = (float (*)[64])band;   // alias: 12*64*4 = 3 KB of 43 KB

    // horizontal pass: 12 x 64
    for (int cell = tid; cell < 12 * 64; cell += 512) {
        int i = cell >> 6, j = cell & 63;
        hT[i][j] = KW0 * (s[i][j] + s[i][j + 4]) +
                   KW1 * (s[i][j + 1] + s[i][j + 3]) + KW2 * s[i][j + 2];
    }
    __syncthreads();

    // vertical pass + clip
    int tx = tid & 63, ty = tid >> 6;
    float acc = KW0 * (hT[ty][tx] + hT[ty + 4][tx]) +
                KW1 * (hT[ty + 1][tx] + hT[ty + 3][tx]) + KW2 * hT[ty + 2][tx];
    acc = fminf(fmaxf(acc, 0.0f), 1.0f);
    out[(by + ty) * WW + (bx + tx)] = acc;
}

// ---------------------------------------------------------------------------
extern "C" void kernel_launch(void* const* d_in, const int* in_sizes, int n_in,
                              void* d_out, int out_size) {
    const float* img = (const float*)d_in[0];
    const int4* offs4 = (const int4*)d_in[1];   // (145924, 2) int32 pairs, 16B-aligned
    float* out = (float*)d_out;

    fused1_kernel<<<SIM_BLOCKS + BLUR_BLOCKS, 256>>>(img, offs4);

    dim3 blk(512);
    dim3 grd(WW / 64, HH / 8);
    final_kernel<<<grd, blk>>>(out);
}

// round 8
// speedup vs baseline: 1.3420x; 1.0052x over previous
#include <cuda_runtime.h>

#define HH 384
#define WW 384
#define NPIX (HH * WW)
#define NSW 382     // swaps per row sweep (w = 383..2)
#define NROWS 382   // row sweeps (h = 383..2)

#define SIM_BLOCKS 48          // 8 sweeps per block
#define BLUR_BLOCKS (12 * 48)  // 32x8 tiles for blur1

#define NSTRIP 28              // strips staged per final block

// Scratch (static __device__ globals: allocation-free)
__device__ float g_B1[NPIX];                        // blurred input
__device__ unsigned short g_A16[NROWS * 2 * WW];    // strip perms, compressed:
                                                    // bit15 = stays-on-row-h, bits[0:9] = column

// Gaussian weights: sigma=0.4, radius=2, normalized
#define K0D 3.726653172078671e-06
#define K1D 0.04393693362340742
#define KSUM (1.0 + 2.0 * (K0D + K1D))
#define KW0 ((float)(K0D / KSUM))
#define KW1 ((float)(K1D / KSUM))
#define KW2 ((float)(1.0 / KSUM))

__device__ __forceinline__ unsigned short enc_idx(int idx, int h) {
    int stay = idx >= h * WW;
    int col = idx - (stay ? h * WW : (h - 1) * WW);
    return (unsigned short)(col | (stay << 15));
}

// ---------------------------------------------------------------------------
// K1 (merged): blocks [0,48) = warp-parallel sweep sim; rest = blur1.
// ---------------------------------------------------------------------------
__global__ __launch_bounds__(256) void fused1_kernel(const float* __restrict__ in,
                                                     const int4* __restrict__ offs4) {
    __shared__ float s[12][40];
    __shared__ float hT[12][32];
    __shared__ unsigned char sOff[8 * 384];
    __shared__ __align__(16) unsigned short sStrip[8 * 2 * WW];   // 12 KB

    int tid = threadIdx.x;

    if (blockIdx.x < SIM_BLOCKS) {
        // Stage offsets coalesced; 1 byte/step: bit0=(dx!=0), bit1=(dy!=0).
        int base4 = blockIdx.x * 8 * 191;
        for (int t = tid; t < 8 * 191; t += 256) {
            if (base4 + t < NROWS * 191) {
                int4 v = offs4[base4 + t];
                int ls = t / 191, st = (t - ls * 191) * 2;
                unsigned b0 = (v.x ? 1u : 0u) | (v.y ? 2u : 0u);
                unsigned b1 = (v.z ? 1u : 0u) | (v.w ? 2u : 0u);
                *(unsigned short*)&sOff[ls * 384 + st] = (unsigned short)(b0 | (b1 << 8));
            }
        }
        __syncthreads();

        int wl = tid >> 5, lane = tid & 31;
        int u = blockIdx.x * 8 + wl;

        if (u < NROWS) {
            int h = 383 - u;
            int s0 = 12 * lane;
            int cnt = min(NSW - s0, 12);               // lane 31 -> 10

            const unsigned* fp = (const unsigned*)&sOff[wl * 384 + s0];
            unsigned q0 = fp[0], q1 = fp[1], q2 = fp[2];
            unsigned mpx = 0, mpy = 0;
#pragma unroll
            for (int j = 0; j < 4; j++) {
                mpx |= ((q0 >> (8 * j)) & 1u) << j;
                mpy |= ((q0 >> (8 * j + 1)) & 1u) << j;
                mpx |= ((q1 >> (8 * j)) & 1u) << (j + 4);
                mpy |= ((q1 >> (8 * j + 1)) & 1u) << (j + 4);
                mpx |= ((q2 >> (8 * j)) & 1u) << (j + 8);
                mpy |= ((q2 >> (8 * j + 1)) & 1u) << (j + 8);
            }
            unsigned valid = (cnt >= 12) ? 0xFFFu : ((1u << cnt) - 1u);
            unsigned mrst = (~(mpx & ~mpy)) & valid;   // steps where A resets
            int lr_full = mrst ? (s0 + 31 - __clz(mrst)) : -1;
            unsigned m2 = mrst & ~(1u << (cnt - 1));
            int lr_excl = m2 ? (s0 + 31 - __clz(m2)) : -1;

            int v = lr_full;
#pragma unroll
            for (int off = 1; off < 32; off <<= 1) {
                int t = __shfl_up_sync(0xFFFFFFFFu, v, off);
                if (lane >= off) v = max(v, t);
            }
            int R_in = __shfl_up_sync(0xFFFFFFFFu, v, 1);
            if (lane == 0) R_in = -1;

            int A = h * WW + 382 - R_in;

            int myA_last = h * WW + 382 - max(R_in, lr_excl);
            unsigned pxl = (mpx >> (cnt - 1)) & 1u, pyl = (mpy >> (cnt - 1)) & 1u;
            int pack = (myA_last << 2) | (int)(pxl << 1) | (int)pyl;
            int prev = __shfl_up_sync(0xFFFFFFFFu, pack, 1);

            int B;
            if (lane == 0) {
                B = (h - 1) * WW + 383;
            } else {
                int A_pl = prev >> 2;
                bool ppx = (prev >> 1) & 1, ppy = prev & 1;
                B = (ppx && ppy) ? A_pl : ((h - 1) * WW + 383 - s0);
            }

            unsigned short* __restrict__ A0 = sStrip + wl * (2 * WW);   // row h-1
            unsigned short* __restrict__ A1 = A0 + WW;                  // row h
#pragma unroll
            for (int j = 0; j < 12; j++) {
                if (j >= cnt) break;
                int stp = s0 + j, w = 383 - stp;
                int c = h * WW + (w - 1);
                int d = c - WW;
                bool pX = (mpx >> j) & 1u;
                bool pY = (mpy >> j) & 1u;
                int fa = pX ? (pY ? d : c) : (pY ? B : A);
                int fb = (!pX && pY) ? A : B;
                A1[w] = enc_idx(fa, h);
                A0[w] = enc_idx(fb, h);
                int nA = (pX && !pY) ? A : c;
                B = (pX && pY) ? A : d;
                A = nA;
            }
            if (lane == 31) {
                A1[1] = enc_idx(A, h); A0[1] = enc_idx(B, h);
                A1[0] = (unsigned short)0x8000u; A0[0] = 0;
            }
        }
        __syncthreads();

        // coalesced flush: 8 strips x 96 uint4 = 768 uint4 (3 per thread)
        {
            int base = blockIdx.x * 768;               // uint4 units into g_A16
            const uint4* src = (const uint4*)sStrip;
            uint4* dst = (uint4*)g_A16;
            for (int t = tid; t < 768; t += 256) {
                if (base + t < NROWS * 96) dst[base + t] = src[t];
            }
        }
    } else {
        // blur1: two-pass separable gaussian (edge replicate) : in -> g_B1
        int bi = blockIdx.x - SIM_BLOCKS;
        int bx = (bi % 12) * 32, by = (bi / 12) * 8;
        int tx = tid & 31, ty = tid >> 5;

        for (int cell = tid; cell < 12 * 36; cell += 256) {
            int i = cell / 36, j = cell - i * 36;
            int gr = min(max(by + i - 2, 0), HH - 1);
            int gc = min(max(bx + j - 2, 0), WW - 1);
            s[i][j] = in[gr * WW + gc];
        }
        __syncthreads();

        for (int cell = tid; cell < 12 * 32; cell += 256) {
            int i = cell >> 5, j = cell & 31;
            hT[i][j] = KW0 * (s[i][j] + s[i][j + 4]) +
                       KW1 * (s[i][j + 1] + s[i][j + 3]) + KW2 * s[i][j + 2];
        }
        __syncthreads();

        float acc = KW0 * (hT[ty][tx] + hT[ty + 4][tx]) +
                    KW1 * (hT[ty + 1][tx] + hT[ty + 3][tx]) + KW2 * hT[ty + 2][tx];
        g_B1[(by + ty) * WW + (bx + tx)] = acc;
    }
}

// ---------------------------------------------------------------------------
// Rare global-fallback continuation of a chain beyond the staged band.
// Enter with walker on row (h_enter - 1), column c.
// ---------------------------------------------------------------------------
__device__ __noinline__ int walk_global(int h_enter, int c) {
    int h = h_enter, rho = h_enter - 1;
    while (h <= 383) {
        unsigned e = g_A16[(383 - h) * (2 * WW) + (rho - (h - 1)) * WW + c];
        c = e & 511;
        if (e & 0x8000u) { rho = h; h++; }
        else { rho = h - 1; break; }
    }
    return rho * WW + c;
}

// ---------------------------------------------------------------------------
// K2: 64x8 tiles, 512 threads. Stage strip band -> dual-chain walk-gather ->
// two-pass gaussian blur -> clip -> out.
// Band coordinates: strip h lives at band rows (h_hi-h)*2 + {0,1} (384 ushort
// per row). First hop reads local row 1 (or 0 when gr==1); every later hop
// reads local row 0, so a hop is: e=band[idx]; c=e&511; stay? bb-=2 : done.
// hT aliases band (dead after walks) to stay under the 48 KB static limit.
// ---------------------------------------------------------------------------
__global__ __launch_bounds__(512) void final_kernel(float* __restrict__ out) {
    __shared__ float s[12][72];
    __shared__ __align__(16) unsigned short band[NSTRIP * 2 * WW];  // 43 KB
    int bx = blockIdx.x * 64, by = blockIdx.y * 8;
    int tid = threadIdx.x;

    int h_lo = (by - 2 < 2) ? 2 : (by - 2);
    int n_h = min(NSTRIP, 384 - h_lo);
    int h_hi = h_lo + n_h - 1;
    int u_min = 383 - h_hi;

    // contiguous vectorized band copy: n_h strips x 96 uint4 each
    {
        const uint4* gsrc = (const uint4*)(g_A16) + (size_t)u_min * 96;
        uint4* bdst = (uint4*)band;
        int tot = n_h * 96;
        for (int t = tid; t < tot; t += 512) bdst[t] = gsrc[t];
    }
    __syncthreads();

    // ---- dual-chain walk: thread owns cells tid and tid+512 of 12x68 ----
    {
        int cell0 = tid, cell1 = tid + 512;
        bool act1 = (cell1 < 12 * 68);

        int i0 = cell0 / 68, j0 = cell0 - i0 * 68;
        int gr0 = min(max(by + i0 - 2, 0), HH - 1);
        int gc0 = min(max(bx + j0 - 2, 0), WW - 1);
        int i1 = 0, j1 = 0, gr1 = 0, gc1 = 0;
        if (act1) {
            i1 = cell1 / 68; j1 = cell1 - i1 * 68;
            gr1 = min(max(by + i1 - 2, 0), HH - 1);
            gc1 = min(max(bx + j1 - 2, 0), WW - 1);
        }

        // init chain state: done/fallback flags, band index, column, base
        int c0 = gc0, bb0 = 0, idx0 = 0, src0 = gc0;
        bool d0 = (gr0 == 0), f0 = false;
        if (!d0) {
            int h0 = (gr0 < 2) ? 2 : gr0;
            int lr = gr0 - (h0 - 1);               // 1 normally, 0 for gr0==1
            bb0 = (h_hi - h0) * 2;
            idx0 = (bb0 + lr) * WW + c0;
        }
        int c1 = gc1, bb1 = 0, idx1 = 0, src1 = gc1;
        bool d1 = (!act1) || (gr1 == 0), f1 = false;
        if (!d1) {
            int h1 = (gr1 < 2) ? 2 : gr1;
            int lr = gr1 - (h1 - 1);
            bb1 = (h_hi - h1) * 2;
            idx1 = (bb1 + lr) * WW + c1;
        }

        while (!(d0 && d1)) {
            unsigned e0 = 0, e1 = 0;
            if (!d0) e0 = band[idx0];
            if (!d1) e1 = band[idx1];
            if (!d0) {
                c0 = e0 & 511;
                if (e0 & 0x8000u) {
                    bb0 -= 2;
                    if (bb0 < 0) { f0 = true; d0 = true; }
                    else idx0 = bb0 * WW + c0;
                } else {
                    src0 = (h_hi - (bb0 >> 1) - 1) * WW + c0;
                    d0 = true;
                }
            }
            if (!d1) {
                c1 = e1 & 511;
                if (e1 & 0x8000u) {
                    bb1 -= 2;
                    if (bb1 < 0) { f1 = true; d1 = true; }
                    else idx1 = bb1 * WW + c1;
                } else {
                    src1 = (h_hi - (bb1 >> 1) - 1) * WW + c1;
                    d1 = true;
                }
            }
        }
        if (f0) src0 = walk_global(h_hi + 1, c0);
        if (f1) src1 = walk_global(h_hi + 1, c1);

        // batched gathers (MLP 2), then STS
        float v0 = g_B1[src0];
        float v1 = act1 ? g_B1[src1] : 0.0f;
        s[i0][j0] = v0;
        if (act1) s[i1][j1] = v1;
    }
    __syncthreads();   // all walks done -> band storage reusable

    float (*hT)[64] = (float (*)[64])band;   // alias: 12*64*4 = 3 KB of 43 KB

    // horizontal pass: 12 x 64
    for (int cell = tid; cell < 12 * 64; cell += 512) {
        int i = cell >> 6, j = cell & 63;
        hT[i][j] = KW0 * (s[i][j] + s[i][j + 4]) +
                   KW1 * (s[i][j + 1] + s[i][j + 3]) + KW2 * s[i][j + 2];
    }
    __syncthreads();

    // vertical pass + clip
    int tx = tid & 63, ty = tid >> 6;
    float acc = KW0 * (hT[ty][tx] + hT[ty + 4][tx]) +
                KW1 * (hT[ty + 1][tx] + hT[ty + 3][tx]) + KW2 * hT[ty + 2][tx];
    acc = fminf(fmaxf(acc, 0.0f), 1.0f);
    out[(by + ty) * WW + (bx + tx)] = acc;
}

// ---------------------------------------------------------------------------
extern "C" void kernel_launch(void* const* d_in, const int* in_sizes, int n_in,
                              void* d_out, int out_size) {
    const float* img = (const float*)d_in[0];
    const int4* offs4 = (const int4*)d_in[1];   // (145924, 2) int32 pairs, 16B-aligned
    float* out = (float*)d_out;

    fused1_kernel<<<SIM_BLOCKS + BLUR_BLOCKS, 256>>>(img, offs4);

    dim3 blk(512);
    dim3 grd(WW / 64, HH / 8);
    final_kernel<<<grd, blk>>>(out);
}